// round 13
// baseline (speedup 1.0000x reference)
#include <cuda_runtime.h>
#include <cuda_bf16.h>
#include <cstdint>
#include <math.h>

// Problem constants
#define Bq 128
#define Tq 2048
#define Dq 128
#define Hq 512
#define Lq 10

// Geometry: 128 blocks = 4 batch groups (bt) x 32 col tiles (nt).
// Block: M=32 rows, N=64 cols (gate*16+jj), K=640 (h 512 + x 128 local).
// 8 warps: wk = wid&1 (k parity), wn = wid>>1 (16-col gate tile).
#define NBLK 128
#define NT 256
#define KH 512
#define KC 128
#define WPAD 648           // W row stride bf16 (1296B = odd*16)
#define APADB 272          // A row stride bytes (odd*16)
#define GPAD 66            // gates partial stride (floats)

// Shared memory map (bytes)
#define OFF_W 0
#define W_SEL (64*WPAD*2)              // 82944 (hi -> lo)
#define OFF_S0 165888
#define A_SEL 8704                     // 32*APADB
#define A_SLOT (2*A_SEL)               // 17408
#define OFF_S1 (OFF_S0 + A_SLOT)       // 183296
#define OFF_X  (OFF_S1 + A_SLOT)       // 200704
#define G_SEL  (32*GPAD*4)             // 8448 (overlays slots)
#define SMEM_BYTES (OFF_X + A_SLOT + 1024)   // 219136

typedef unsigned short u16;
typedef unsigned int u32;

__device__ u16 g_Ahi[2][Bq * KH];      // h only (x is block-local now)
__device__ u16 g_Alo[2][Bq * KH];
__device__ u16 g_Wb[32][2 * 64 * WPAD];
__device__ unsigned g_barc[16 * 32];   // [bt*4+chunk]*32, cumulative counters

// ---------------------------------------------------------------------------
__device__ __forceinline__ void split_bf16(float v, u16& hi, u16& lo) {
    __nv_bfloat16 h = __float2bfloat16_rn(v);
    hi = __bfloat16_as_ushort(h);
    lo = __bfloat16_as_ushort(__float2bfloat16_rn(v - __bfloat162float(h)));
}

__global__ void init_kernel(const float* __restrict__ W_ih,
                            const float* __restrict__ W_hh) {
    unsigned idx = blockIdx.x * blockDim.x + threadIdx.x;
    unsigned stride = gridDim.x * blockDim.x;
    if (idx < 16 * 32) g_barc[idx] = 0u;
    for (unsigned i = idx; i < Bq * KH; i += stride) {
        g_Ahi[0][i] = 0; g_Alo[0][i] = 0;
    }
    // W: col n = gate*16 + jj -> W row gate*512 + nt*16 + jj; k 0..639
    const unsigned total = 32u * 64u * 640u;
    for (unsigned i = idx; i < total; i += stride) {
        unsigned nt = i / (64u * 640u);
        unsigned r = i - nt * (64u * 640u);
        unsigned n = r / 640u, k = r - n * 640u;
        unsigned row = (n >> 4) * Hq + nt * 16 + (n & 15u);
        float w = (k < Hq) ? W_hh[row * Hq + k] : W_ih[row * Dq + (k - Hq)];
        u16 hi, lo; split_bf16(w, hi, lo);
        g_Wb[nt][n * WPAD + k] = hi;
        g_Wb[nt][64 * WPAD + n * WPAD + k] = lo;
    }
}

// ---------------------------------------------------------------------------
__device__ __forceinline__ void ldsm4(u32* r, unsigned addr) {
    asm volatile("ldmatrix.sync.aligned.m8n8.x4.shared.b16 {%0,%1,%2,%3}, [%4];"
                 : "=r"(r[0]), "=r"(r[1]), "=r"(r[2]), "=r"(r[3]) : "r"(addr));
}
__device__ __forceinline__ void mma16816(float* d, const u32* a, const u32* b) {
    asm volatile(
        "mma.sync.aligned.m16n8k16.row.col.f32.bf16.bf16.f32 "
        "{%0,%1,%2,%3}, {%4,%5,%6,%7}, {%8,%9}, {%0,%1,%2,%3};"
        : "+f"(d[0]), "+f"(d[1]), "+f"(d[2]), "+f"(d[3])
        : "r"(a[0]), "r"(a[1]), "r"(a[2]), "r"(a[3]), "r"(b[0]), "r"(b[1]));
}
__device__ __forceinline__ float sigm(float v) { return 1.f / (1.f + __expf(-v)); }
__device__ __forceinline__ float tanh_fast(float v) { return 1.f - 2.f / (__expf(2.f * v) + 1.f); }

__device__ __forceinline__ void spin_acq(const unsigned* p, unsigned target) {
    unsigned v;
    do {
        asm volatile("ld.acquire.gpu.global.u32 %0, [%1];" : "=r"(v) : "l"(p) : "memory");
    } while (v < target);
}
// Warp-collective chunk wait: leader spins, warp follows.
__device__ __forceinline__ void warp_wait(const unsigned* p, unsigned target, int lane) {
    if (lane == 0) spin_acq(p, target);
    __syncwarp();
}

// Copy h chunk c (hi+lo, 16KB) into a slot: 256 threads x 4 cp.async.
__device__ __forceinline__ void copy_chunk(unsigned dstbase, int c, const u16* Ah,
                                           const u16* Al, int bbase, int tid) {
    int row = tid >> 3, kgb = (tid & 7) * 2;
    const u16* sh = Ah + (size_t)(bbase + row) * KH + c * KC + kgb * 8;
    const u16* sl = Al + (size_t)(bbase + row) * KH + c * KC + kgb * 8;
    unsigned d = dstbase + row * APADB + kgb * 16;
    asm volatile("cp.async.cg.shared.global [%0], [%1], 16;\n" :: "r"(d), "l"(sh) : "memory");
    asm volatile("cp.async.cg.shared.global [%0], [%1], 16;\n" :: "r"(d + 16), "l"(sh + 8) : "memory");
    asm volatile("cp.async.cg.shared.global [%0], [%1], 16;\n" :: "r"(d + A_SEL), "l"(sl) : "memory");
    asm volatile("cp.async.cg.shared.global [%0], [%1], 16;\n" :: "r"(d + A_SEL + 16), "l"(sl + 8) : "memory");
    asm volatile("cp.async.commit_group;\n" ::: "memory");
}

// One k16 of the 3-term GEMM (6 ldsm + 12 MMA). acc[mt*2+nsub][4].
__device__ __forceinline__ void k16_step(unsigned ab, unsigned ka, unsigned wkb,
                                         float acc[4][4], unsigned a_off,
                                         unsigned wb_hi, unsigned wb_lo) {
    u32 ah0[4], ah1[4], al0[4], al1[4], wh[4], wl[4];
    unsigned ahi = ab + a_off + ka;
    ldsm4(ah0, ahi);
    ldsm4(ah1, ahi + 16 * APADB);
    ldsm4(al0, ahi + A_SEL);
    ldsm4(al1, ahi + A_SEL + 16 * APADB);
    ldsm4(wh, wb_hi + wkb);
    ldsm4(wl, wb_lo + wkb);
    mma16816(acc[0], ah0, wh);  mma16816(acc[1], ah0, wh + 2);
    mma16816(acc[2], ah1, wh);  mma16816(acc[3], ah1, wh + 2);
    mma16816(acc[0], ah0, wl);  mma16816(acc[1], ah0, wl + 2);
    mma16816(acc[2], ah1, wl);  mma16816(acc[3], ah1, wl + 2);
    mma16816(acc[0], al0, wh);  mma16816(acc[1], al0, wh + 2);
    mma16816(acc[2], al1, wh);  mma16816(acc[3], al1, wh + 2);
}

// Convert this block's x slice for step tt into the local x slot.
__device__ __forceinline__ void conv_x(const float* __restrict__ x, char* sm,
                                       int tt, int bbase, int tid) {
    int row = tid >> 3, seg8 = tid & 7;       // 16 floats per thread
    const float* src = x + ((size_t)(bbase + row) * Tq + tt) * Dq + seg8 * 16;
    float f[16];
#pragma unroll
    for (int j = 0; j < 4; j++) *(float4*)&f[j * 4] = ((const float4*)src)[j];
    u16 hi[16], lo[16];
#pragma unroll
    for (int e = 0; e < 16; e++) split_bf16(f[e], hi[e], lo[e]);
    char* dh = sm + OFF_X + row * APADB + seg8 * 32;
    *(uint4*)dh = ((uint4*)hi)[0];
    *(uint4*)(dh + 16) = ((uint4*)hi)[1];
    *(uint4*)(dh + A_SEL) = ((uint4*)lo)[0];
    *(uint4*)(dh + A_SEL + 16) = ((uint4*)lo)[1];
}

// ---------------------------------------------------------------------------
__global__ __launch_bounds__(NT, 1)
void lstm_kernel(const float* __restrict__ x,
                 const float* __restrict__ bias,
                 const float* __restrict__ Wout,
                 float* __restrict__ out) {
    extern __shared__ char smraw[];
    char* sm = (char*)(((uintptr_t)smraw + 1023) & ~(uintptr_t)1023);
    unsigned smb = (unsigned)__cvta_generic_to_shared(sm);

    const int tid = threadIdx.x;
    const int lane = tid & 31;
    const int wid = tid >> 5;
    const int wk = wid & 1;
    const int wn = wid >> 1;
    const int blk = blockIdx.x;
    const int bt = blk >> 5, nt = blk & 31;
    const int bbase = bt * 32;
    unsigned* bars = &g_barc[bt * 4 * 32];            // 4 chunk counters
    unsigned* mybar = &bars[(nt >> 3) * 32];          // this block produces chunk nt>>3

    // Resident W
    {
        const u16* src = g_Wb[nt];
#pragma unroll 1
        for (int i = tid; i < (2 * 64 * WPAD) / 8; i += NT) {
            asm volatile("cp.async.cg.shared.global [%0], [%1], 16;\n"
                         :: "r"(smb + OFF_W + i * 16), "l"(src + i * 8) : "memory");
        }
        asm volatile("cp.async.commit_group;\n" ::: "memory");
    }

    // ldmatrix per-lane offsets
    const unsigned a_off = (lane & 15) * APADB + (lane >> 4) * 16;
    const unsigned w_row = (lane & 7) | ((lane >> 4) << 3);
    const unsigned w_half = ((lane >> 3) & 1) * 16;
    const unsigned wb_hi = smb + OFF_W + (wn * 16 + w_row) * (WPAD * 2) + w_half;
    const unsigned wb_lo = wb_hi + W_SEL;
    const unsigned slotb[2] = { smb + OFF_S0, smb + OFF_S1 };
    const unsigned xb = smb + OFF_X;

    // Bias + register cell state (cells: b = q*16 + tid>>4, jj = tid&15)
    const int jj_e = tid & 15;
    float bias_r[4], creg[2];
#pragma unroll
    for (int g = 0; g < 4; g++) bias_r[g] = bias[g * Hq + nt * 16 + jj_e];
    creg[0] = 0.f; creg[1] = 0.f;

    asm volatile("cp.async.wait_group 0;\n" ::: "memory");
    conv_x(x, sm, 0, bbase, tid);     // prefill x(0)
    __syncthreads();

    float* gp0 = (float*)(sm + OFF_S0);   // gates partials overlay A slots
    float* gp1 = (float*)(sm + OFF_S1);
    float* gpw = wk ? gp1 : gp0;

#pragma unroll 1
    for (int t = 0; t < Tq; ++t) {
        const int p = t & 1;
        const u16* Ah = g_Ahi[p];
        const u16* Al = g_Alo[p];
        const unsigned target = (unsigned)t * 8u;

        // Get h chunks 0,1 in flight (spins pass once their 8 producers arrived)
        warp_wait(&bars[0], target, lane);
        copy_chunk(slotb[0], 0, Ah, Al, bbase, tid);
        warp_wait(&bars[32], target, lane);
        copy_chunk(slotb[1], 1, Ah, Al, bbase, tid);

        float acc[4][4];
#pragma unroll
        for (int i = 0; i < 4; i++)
#pragma unroll
            for (int j = 0; j < 4; j++) acc[i][j] = 0.f;

        // x chunk first: no cross-block dependency, covers h latency
#pragma unroll
        for (int s = 0; s < 4; s++) {
            const unsigned ka = (unsigned)(2 * s + wk) * 32;
            k16_step(xb, ka, 1024 + ka, acc, a_off, wb_hi, wb_lo);
        }

        // h chunks with per-chunk producer waits
#pragma unroll 1
        for (int c = 0; c < 4; ++c) {
            if (c < 3) asm volatile("cp.async.wait_group 1;\n" ::: "memory");
            else       asm volatile("cp.async.wait_group 0;\n" ::: "memory");
            __syncthreads();
            const unsigned ab = slotb[c & 1];
            const unsigned kb2 = (unsigned)c * 256;
#pragma unroll
            for (int s = 0; s < 4; s++) {
                const unsigned ka = (unsigned)(2 * s + wk) * 32;
                k16_step(ab, ka, kb2 + ka, acc, a_off, wb_hi, wb_lo);
            }
            __syncthreads();
            if (c < 2) {
                warp_wait(&bars[(c + 2) * 32], target, lane);
                copy_chunk(slotb[c & 1], c + 2, Ah, Al, bbase, tid);
            }
        }

        // Stage per-k-parity partial gates (slots are dead now)
#pragma unroll
        for (int mt = 0; mt < 2; mt++)
#pragma unroll
            for (int nsub = 0; nsub < 2; nsub++) {
                const float* a4 = acc[mt * 2 + nsub];
                int m = mt * 16 + (lane >> 2);
                int col = wn * 16 + nsub * 8 + (lane & 3) * 2;
                *(float2*)&gpw[m * GPAD + col] = make_float2(a4[0], a4[1]);
                *(float2*)&gpw[(m + 8) * GPAD + col] = make_float2(a4[2], a4[3]);
            }

        // Convert x(t+1) into the local x slot (x MMAs for step t are done)
        if (t + 1 < Tq) conv_x(x, sm, t + 1, bbase, tid);
        __syncthreads();

        // Elementwise LSTM: 2 cells per thread, c in registers
#pragma unroll
        for (int q = 0; q < 2; q++) {
            int b = q * 16 + (tid >> 4);
            int gb = b * GPAD + jj_e;
            float gi = gp0[gb]      + gp1[gb]      + bias_r[0];
            float gf = gp0[gb + 16] + gp1[gb + 16] + bias_r[1];
            float gg = gp0[gb + 32] + gp1[gb + 32] + bias_r[2];
            float go = gp0[gb + 48] + gp1[gb + 48] + bias_r[3];
            float cn = sigm(gf) * creg[q] + sigm(gi) * tanh_fast(gg);
            creg[q] = cn;
            float h = sigm(go) * tanh_fast(cn);
            u16 hi, lo; split_bf16(h, hi, lo);
            size_t gidx = (size_t)(bbase + b) * KH + nt * 16 + jj_e;
            g_Ahi[p ^ 1][gidx] = hi;
            g_Alo[p ^ 1][gidx] = lo;
        }

        // Producer arrival for our chunk (cumulative counter)
        __threadfence();
        __syncthreads();
        if (tid == 0) atomicAdd(mybar, 1u);
    }

    // Output head: nt==0 block per group. Final h = parity 0 (Tq even).
    if (nt == 0) {
        if (tid < 4) spin_acq(&bars[tid * 32], (unsigned)Tq * 8u);
        __syncthreads();
        float* hst = (float*)sm;            // 32x512 fp32 (over W region)
        float* lst = hst + 32 * Hq;
        for (int i = tid; i < 32 * Hq; i += NT) {
            int b = i >> 9, k = i & 511;
            size_t gi = (size_t)(bbase + b) * KH + k;
            hst[i] = __bfloat162float(__ushort_as_bfloat16(g_Ahi[0][gi])) +
                     __bfloat162float(__ushort_as_bfloat16(g_Alo[0][gi]));
        }
        __syncthreads();
        for (int q = tid; q < 32 * Lq; q += NT) {
            int b = q / Lq, l = q - b * Lq;
            const float* hr = hst + b * Hq;
            const float* wr = Wout + l * Hq;
            float s = 0.f;
            for (int k = 0; k < Hq; k++) s += hr[k] * wr[k];
            lst[q] = s;
        }
        __syncthreads();
        if (tid < 32) {
            int b = tid;
            float m = -1e30f;
            for (int l = 0; l < Lq; l++) m = fmaxf(m, lst[b * Lq + l]);
            float e[Lq]; float ssum = 0.f;
            for (int l = 0; l < Lq; l++) { e[l] = expf(lst[b * Lq + l] - m); ssum += e[l]; }
            float inv = 1.f / ssum;
            for (int l = 0; l < Lq; l++) out[(bbase + b) * Lq + l] = e[l] * inv;
        }
    }
}

extern "C" void kernel_launch(void* const* d_in, const int* in_sizes, int n_in,
                              void* d_out, int out_size) {
    const float* x     = (const float*)d_in[0];
    const float* W_ih  = (const float*)d_in[1];
    const float* W_hh  = (const float*)d_in[2];
    const float* b     = (const float*)d_in[3];
    const float* W_out = (const float*)d_in[4];
    float* out = (float*)d_out;

    cudaFuncSetAttribute(lstm_kernel,
                         cudaFuncAttributeMaxDynamicSharedMemorySize, SMEM_BYTES);

    init_kernel<<<256, 256>>>(W_ih, W_hh);
    lstm_kernel<<<NBLK, NT, SMEM_BYTES>>>(x, b, W_out, out);
}